// round 12
// baseline (speedup 1.0000x reference)
#include <cuda_runtime.h>
#include <cstdint>

#define BATCH    1024
#define IN_BITS  4096
#define NUM_LUTS 16384
#define KBITS    6
#define NGROUPS  (BATCH / 32)          // 32 groups of 32 batches
#define LTILE    256                   // luts per block (thread = lut)
#define NTHR     256
#define BCG      4                     // batch-groups per CTA (one LDG.128)

#define PACK_BLOCKS (NGROUPS * (IN_BITS / 256) * 2)   // 1024 (16-row halves)
#define SIGT_BLOCKS (NUM_LUTS / 64)                   // 256 (64-lut patches)
#define CONN_BLOCKS ((NUM_LUTS * KBITS + 255) / 256)  // 384

// g_bitsT[p][g]: bit j of word = batch g*32+j at input column p.
// One column's 32 group-words are contiguous (128 B) -> LDG.128 spans 4 groups.
__device__ uint32_t g_bitsT[IN_BITS * NGROUPS];      // 512 KB
__device__ uint16_t g_conn[NUM_LUTS * KBITS];        // 196 KB
__device__ float    g_sigT[64 * NUM_LUTS];           // 4 MB, TRANSPOSED [idx][lut]

// ---------------------------------------------------------------------------
// Fused prep: [pack | sigmoid+smem-transpose | conn] dispatched on blockIdx.x.
// ---------------------------------------------------------------------------
__global__ void __launch_bounds__(256) prep_kernel(const float* __restrict__ x,
                                                   const float* __restrict__ table,
                                                   const int* __restrict__ conn32) {
    __shared__ float s[64 * 65];
    const int b = blockIdx.x;
    if (b < PACK_BLOCKS) {
        // pack: thread owns (column p, 16-row half); MLP-16 coalesced LDGs;
        // scattered 2B store into the transposed layout (small total traffic).
        const int g    = b >> 5;
        const int rest = b & 31;
        const int half = rest >> 4;
        const int p    = (rest & 15) * 256 + threadIdx.x;
        const float* xp = x + (size_t)(g * 32 + half * 16) * IN_BITS + p;
        uint32_t a = 0;
#pragma unroll
        for (int j = 0; j < 16; ++j)
            a |= (__ldg(xp + (size_t)j * IN_BITS) > 0.5f ? 1u : 0u) << j;
        ((uint16_t*)g_bitsT)[2 * ((size_t)p * NGROUPS + g) + half] = (uint16_t)a;
    } else if (b < PACK_BLOCKS + SIGT_BLOCKS) {
        // 64-lut x 64-idx patch: coalesced read -> sigmoid -> smem transpose
        const int lut0 = (b - PACK_BLOCKS) * 64;
        const int t = threadIdx.x;
#pragma unroll
        for (int k = 0; k < 4; ++k) {
            const int i = t + k * 256;
            const int r = i >> 4;
            const int q = i & 15;
            float4 v = *(const float4*)(table + (size_t)(lut0 + r) * 64 + 4 * q);
            v.x = __fdividef(1.0f, 1.0f + __expf(-v.x));
            v.y = __fdividef(1.0f, 1.0f + __expf(-v.y));
            v.z = __fdividef(1.0f, 1.0f + __expf(-v.z));
            v.w = __fdividef(1.0f, 1.0f + __expf(-v.w));
            s[(4 * q + 0) * 65 + r] = v.x;
            s[(4 * q + 1) * 65 + r] = v.y;
            s[(4 * q + 2) * 65 + r] = v.z;
            s[(4 * q + 3) * 65 + r] = v.w;
        }
        __syncthreads();
#pragma unroll
        for (int k = 0; k < 4; ++k) {
            const int i = t + k * 256;
            const int c = i >> 4;
            const int j = (i & 15) * 4;
            float4 o;
            o.x = s[c * 65 + j + 0];
            o.y = s[c * 65 + j + 1];
            o.z = s[c * 65 + j + 2];
            o.w = s[c * 65 + j + 3];
            *(float4*)(g_sigT + (size_t)c * NUM_LUTS + lut0 + j) = o;
        }
    } else {
        // conn dtype sniff: JAX w/o x64 emits int32 despite int64 annotation;
        // true int64 LE would have all odd words == 0 (values < 4096).
        uint32_t acc = 0;
#pragma unroll
        for (int sI = 1; sI < 64; sI += 2) acc |= (uint32_t)conn32[sI];
        const bool is_i64 = (acc == 0u);
        const int i = (b - PACK_BLOCKS - SIGT_BLOCKS) * 256 + threadIdx.x;
        if (i < NUM_LUTS * KBITS) {
            int v = is_i64 ? conn32[2 * i] : conn32[i];
            g_conn[i] = (uint16_t)v;
        }
    }
}

// ---------------------------------------------------------------------------
// Process one group-word set: 32 outputs of one (lut, group).
// Four 6-bit indices per acc word (bits jj, jj+8, jj+16, jj+24).
// ---------------------------------------------------------------------------
__device__ __forceinline__ void proc_group(uint32_t w0, uint32_t w1, uint32_t w2,
                                           uint32_t w3, uint32_t w4, uint32_t w5,
                                           float* __restrict__ op,
                                           const float* __restrict__ scol) {
#pragma unroll
    for (int jj = 0; jj < 8; ++jj) {
        uint32_t acc =   ((w0 >> jj) & 0x01010101u);
        acc = acc * 2u + ((w1 >> jj) & 0x01010101u);
        acc = acc * 2u + ((w2 >> jj) & 0x01010101u);
        acc = acc * 2u + ((w3 >> jj) & 0x01010101u);
        acc = acc * 2u + ((w4 >> jj) & 0x01010101u);
        acc = acc * 2u + ((w5 >> jj) & 0x01010101u);
        const unsigned i0 = acc & 0xFFu;
        const unsigned i1 = __byte_perm(acc, 0, 0x4441);
        const unsigned i2 = __byte_perm(acc, 0, 0x4442);
        const unsigned i3 = acc >> 24;
        float v0 = scol[i0 * LTILE];       // conflict-free LDS (bank = lane)
        float v1 = scol[i1 * LTILE];
        float v2 = scol[i2 * LTILE];
        float v3 = scol[i3 * LTILE];
        __stcs(op + (size_t)jj * NUM_LUTS, v0);
        __stcs(op + (size_t)(jj + 8)  * NUM_LUTS, v1);
        __stcs(op + (size_t)(jj + 16) * NUM_LUTS, v2);
        __stcs(op + (size_t)(jj + 24) * NUM_LUTS, v3);
    }
}

// ---------------------------------------------------------------------------
// Main LUT kernel — barrier-free. block = 256 (thread = one LUT), grid (64,8).
// smem: ONLY the 64 KB transposed table tile stab[idx][l] (stride 256 -> LDS
// bank = lane -> conflict-free). Bits live in registers: 6 x LDG.128 fetch 4
// group-words per connection. One __syncthreads total; 128 outputs/thread.
// ---------------------------------------------------------------------------
__global__ void __launch_bounds__(NTHR, 3) lut_kernel(float* __restrict__ out) {
    extern __shared__ float stab[];                 // [64][LTILE]

    const int t       = threadIdx.x;
    const int lutbase = blockIdx.x * LTILE;
    const int g0      = blockIdx.y * BCG;
    const int lut     = lutbase + t;

    // Bits for 4 groups x 6 connections: 6 LDG.128 (independent, MLP 6).
    const uint16_t* cq = &g_conn[(size_t)lut * KBITS];
    const uint4 W0 = *(const uint4*)&g_bitsT[(size_t)cq[0] * NGROUPS + g0];
    const uint4 W1 = *(const uint4*)&g_bitsT[(size_t)cq[1] * NGROUPS + g0];
    const uint4 W2 = *(const uint4*)&g_bitsT[(size_t)cq[2] * NGROUPS + g0];
    const uint4 W3 = *(const uint4*)&g_bitsT[(size_t)cq[3] * NGROUPS + g0];
    const uint4 W4 = *(const uint4*)&g_bitsT[(size_t)cq[4] * NGROUPS + g0];
    const uint4 W5 = *(const uint4*)&g_bitsT[(size_t)cq[5] * NGROUPS + g0];

    // Transposed table tile: stab[idx][l] <- g_sigT[idx][lutbase+l].
#pragma unroll
    for (int i = t; i < 64 * (LTILE / 4); i += NTHR) {
        const int idx = i >> 6, c = (i & 63) * 4;
        *(float4*)(stab + idx * LTILE + c) =
            *(const float4*)(g_sigT + (size_t)idx * NUM_LUTS + lutbase + c);
    }
    __syncthreads();

    const float* scol = stab + t;
    float* op = out + (size_t)(g0 * 32) * NUM_LUTS + lut;
    const size_t gstride = (size_t)32 * NUM_LUTS;

    proc_group(W0.x, W1.x, W2.x, W3.x, W4.x, W5.x, op,               scol);
    proc_group(W0.y, W1.y, W2.y, W3.y, W4.y, W5.y, op + gstride,     scol);
    proc_group(W0.z, W1.z, W2.z, W3.z, W4.z, W5.z, op + 2 * gstride, scol);
    proc_group(W0.w, W1.w, W2.w, W3.w, W4.w, W5.w, op + 3 * gstride, scol);
}

// ---------------------------------------------------------------------------
extern "C" void kernel_launch(void* const* d_in, const int* in_sizes, int n_in,
                              void* d_out, int out_size) {
    const float* x    = (const float*)d_in[0];   // (1024, 4096) f32
    const float* tab  = (const float*)d_in[1];   // (16384, 64) f32
    const int*   conn = (const int*)d_in[2];     // (16384, 6) i32 (sniffed)
    float*       out  = (float*)d_out;           // (1024, 16384) f32

    static const int SMEM = 64 * LTILE * 4;      // 65536 B
    cudaFuncSetAttribute(lut_kernel, cudaFuncAttributeMaxDynamicSharedMemorySize, SMEM);

    prep_kernel<<<PACK_BLOCKS + SIGT_BLOCKS + CONN_BLOCKS, 256>>>(x, tab, conn);

    dim3 gridC(NUM_LUTS / LTILE, NGROUPS / BCG);         // (64, 8)
    lut_kernel<<<gridC, NTHR, SMEM>>>(out);
}

// round 13
// speedup vs baseline: 1.1878x; 1.1878x over previous
#include <cuda_runtime.h>
#include <cstdint>

#define BATCH    1024
#define IN_BITS  4096
#define NUM_LUTS 16384
#define KBITS    6
#define NGROUPS  (BATCH / 32)          // 32 groups of 32 batches
#define LTILE    512                   // luts per block (big-smem tile)
#define NTHR     512                   // thread = one LUT
#define BC       8                     // batch-groups per block

#define PACK_BLOCKS (NGROUPS * (IN_BITS / 256) * 2)   // 1024 (16-row halves)
#define SIGT_BLOCKS (NUM_LUTS / 64)                   // 256 (64-lut patches)
#define CONN_BLOCKS ((NUM_LUTS * KBITS + 255) / 256)  // 384

__device__ uint32_t g_bits[NGROUPS][IN_BITS];        // 512 KB
__device__ uint16_t g_conn[NUM_LUTS * KBITS];        // 196 KB
__device__ float    g_sigT[64 * NUM_LUTS];           // 4 MB, TRANSPOSED [idx][lut]

// ---------------------------------------------------------------------------
// Fused prep: [pack | sigmoid+smem-transpose | conn] dispatched on blockIdx.x.
// ---------------------------------------------------------------------------
__global__ void __launch_bounds__(256) prep_kernel(const float* __restrict__ x,
                                                   const float* __restrict__ table,
                                                   const int* __restrict__ conn32) {
    __shared__ float s[64 * 65];
    const int b = blockIdx.x;
    if (b < PACK_BLOCKS) {
        // pack v2: thread owns (column p, 16-row half) -> MLP 16 coalesced LDGs
        const int g    = b >> 5;
        const int rest = b & 31;
        const int half = rest >> 4;
        const int p    = (rest & 15) * 256 + threadIdx.x;
        const float* xp = x + (size_t)(g * 32 + half * 16) * IN_BITS + p;
        uint32_t a = 0;
#pragma unroll
        for (int j = 0; j < 16; ++j)
            a |= (__ldg(xp + (size_t)j * IN_BITS) > 0.5f ? 1u : 0u) << j;
        ((uint16_t*)g_bits)[2 * ((size_t)g * IN_BITS + p) + half] = (uint16_t)a;
    } else if (b < PACK_BLOCKS + SIGT_BLOCKS) {
        // 64-lut x 64-idx patch: coalesced read -> sigmoid -> smem transpose
        const int lut0 = (b - PACK_BLOCKS) * 64;
        const int t = threadIdx.x;
#pragma unroll
        for (int k = 0; k < 4; ++k) {
            const int i = t + k * 256;
            const int r = i >> 4;
            const int q = i & 15;
            float4 v = *(const float4*)(table + (size_t)(lut0 + r) * 64 + 4 * q);
            v.x = __fdividef(1.0f, 1.0f + __expf(-v.x));
            v.y = __fdividef(1.0f, 1.0f + __expf(-v.y));
            v.z = __fdividef(1.0f, 1.0f + __expf(-v.z));
            v.w = __fdividef(1.0f, 1.0f + __expf(-v.w));
            s[(4 * q + 0) * 65 + r] = v.x;
            s[(4 * q + 1) * 65 + r] = v.y;
            s[(4 * q + 2) * 65 + r] = v.z;
            s[(4 * q + 3) * 65 + r] = v.w;
        }
        __syncthreads();
#pragma unroll
        for (int k = 0; k < 4; ++k) {
            const int i = t + k * 256;
            const int c = i >> 4;
            const int j = (i & 15) * 4;
            float4 o;
            o.x = s[c * 65 + j + 0];
            o.y = s[c * 65 + j + 1];
            o.z = s[c * 65 + j + 2];
            o.w = s[c * 65 + j + 3];
            *(float4*)(g_sigT + (size_t)c * NUM_LUTS + lut0 + j) = o;
        }
    } else {
        // conn dtype sniff: JAX w/o x64 emits int32 despite int64 annotation;
        // true int64 LE would have all odd words == 0 (values < 4096).
        uint32_t acc = 0;
#pragma unroll
        for (int sI = 1; sI < 64; sI += 2) acc |= (uint32_t)conn32[sI];
        const bool is_i64 = (acc == 0u);
        const int i = (b - PACK_BLOCKS - SIGT_BLOCKS) * 256 + threadIdx.x;
        if (i < NUM_LUTS * KBITS) {
            int v = is_i64 ? conn32[2 * i] : conn32[i];
            g_conn[i] = (uint16_t)v;
        }
    }
}

// ---------------------------------------------------------------------------
// cp.async helpers
// ---------------------------------------------------------------------------
__device__ __forceinline__ void cp_async16(void* smem_dst, const void* gsrc) {
    uint32_t s = (uint32_t)__cvta_generic_to_shared(smem_dst);
    asm volatile("cp.async.cg.shared.global [%0], [%1], 16;\n" :: "r"(s), "l"(gsrc));
}
__device__ __forceinline__ void cp_async_commit() {
    asm volatile("cp.async.commit_group;\n" ::: "memory");
}
__device__ __forceinline__ void cp_async_wait0() {
    asm volatile("cp.async.wait_group 0;\n" ::: "memory");
}

// ---------------------------------------------------------------------------
// Main LUT kernel — big-smem variant. block = 512 (thread = one LUT),
// grid (32, 4) = 128 CTAs, 1 CTA/SM, single wave.
// smem: 2x16 KB bits (cp.async double-buffered) + 128 KB transposed table
// stab[idx][l] (stride 512 -> LDS bank = lane -> conflict-free) = 160 KB.
// Per tile: ONE gather of 6 words per lut (no batch-half redundancy), then
// 32 outputs from registers. Halves bits L2 traffic vs LTILE=256 (16 MB).
// ---------------------------------------------------------------------------
__global__ void __launch_bounds__(NTHR, 1) lut_kernel(float* __restrict__ out) {
    extern __shared__ uint32_t smem[];
    uint32_t* sb0  = smem;                          // bits buffer 0
    uint32_t* sb1  = smem + IN_BITS;                // bits buffer 1
    float*    stab = (float*)(smem + 2 * IN_BITS);  // [64][LTILE]

    const int t       = threadIdx.x;
    const int lutbase = blockIdx.x * LTILE;
    const int g0      = blockIdx.y * BC;
    const int lut     = lutbase + t;

    // Prefetch g0's bit column (async).
    {
        const uint4* src = (const uint4*)g_bits[g0];
#pragma unroll
        for (int i = t; i < IN_BITS / 4; i += NTHR)
            cp_async16((uint4*)sb0 + i, src + i);
        cp_async_commit();
    }

    // Transposed table tile: stab[idx][l] <- g_sigT[idx][lutbase+l].
    {
#pragma unroll
        for (int i = t; i < 64 * (LTILE / 4); i += NTHR) {
            const int idx = i >> 7, c = (i & 127) * 4;
            *(float4*)(stab + idx * LTILE + c) =
                *(const float4*)(g_sigT + (size_t)idx * NUM_LUTS + lutbase + c);
        }
    }

    const uint16_t* cp = &g_conn[(size_t)lut * KBITS];
    const int c0 = cp[0], c1 = cp[1], c2 = cp[2], c3 = cp[3], c4 = cp[4], c5 = cp[5];
    const float* scol = stab + t;                   // this LUT's column

    cp_async_wait0();
    __syncthreads();

#pragma unroll 1
    for (int g = g0; g < g0 + BC; ++g) {
        uint32_t* cur = ((g - g0) & 1) ? sb1 : sb0;
        uint32_t* nxt = ((g - g0) & 1) ? sb0 : sb1;

        if (g + 1 < g0 + BC) {
            const uint4* src = (const uint4*)g_bits[g + 1];
#pragma unroll
            for (int i = t; i < IN_BITS / 4; i += NTHR)
                cp_async16((uint4*)nxt + i, src + i);
            cp_async_commit();
        }

        const uint32_t w0 = cur[c0], w1 = cur[c1], w2 = cur[c2];
        const uint32_t w3 = cur[c3], w4 = cur[c4], w5 = cur[c5];

        float* op = out + (size_t)(g * 32) * NUM_LUTS + lut;
#pragma unroll
        for (int jj = 0; jj < 8; ++jj) {
            // four 6-bit indices at once (bits jj, jj+8, jj+16, jj+24)
            uint32_t acc =   ((w0 >> jj) & 0x01010101u);
            acc = acc * 2u + ((w1 >> jj) & 0x01010101u);
            acc = acc * 2u + ((w2 >> jj) & 0x01010101u);
            acc = acc * 2u + ((w3 >> jj) & 0x01010101u);
            acc = acc * 2u + ((w4 >> jj) & 0x01010101u);
            acc = acc * 2u + ((w5 >> jj) & 0x01010101u);
            const unsigned i0 = acc & 0xFFu;
            const unsigned i1 = __byte_perm(acc, 0, 0x4441);
            const unsigned i2 = __byte_perm(acc, 0, 0x4442);
            const unsigned i3 = acc >> 24;
            float v0 = scol[i0 * LTILE];            // conflict-free LDS
            float v1 = scol[i1 * LTILE];
            float v2 = scol[i2 * LTILE];
            float v3 = scol[i3 * LTILE];
            __stcs(op + (size_t)jj * NUM_LUTS, v0);
            __stcs(op + (size_t)(jj + 8)  * NUM_LUTS, v1);
            __stcs(op + (size_t)(jj + 16) * NUM_LUTS, v2);
            __stcs(op + (size_t)(jj + 24) * NUM_LUTS, v3);
        }

        cp_async_wait0();
        __syncthreads();
    }
}

// ---------------------------------------------------------------------------
extern "C" void kernel_launch(void* const* d_in, const int* in_sizes, int n_in,
                              void* d_out, int out_size) {
    const float* x    = (const float*)d_in[0];   // (1024, 4096) f32
    const float* tab  = (const float*)d_in[1];   // (16384, 64) f32
    const int*   conn = (const int*)d_in[2];     // (16384, 6) i32 (sniffed)
    float*       out  = (float*)d_out;           // (1024, 16384) f32

    static const int SMEM = (2 * IN_BITS + 64 * LTILE) * 4;  // 163840 B
    cudaFuncSetAttribute(lut_kernel, cudaFuncAttributeMaxDynamicSharedMemorySize, SMEM);

    prep_kernel<<<PACK_BLOCKS + SIGT_BLOCKS + CONN_BLOCKS, 256>>>(x, tab, conn);

    dim3 gridC(NUM_LUTS / LTILE, NGROUPS / BC);          // (32, 4)
    lut_kernel<<<gridC, NTHR, SMEM>>>(out);
}